// round 1
// baseline (speedup 1.0000x reference)
#include <cuda_runtime.h>
#include <math.h>

#define LL 512
#define DD 256
#define PP 128
#define HH 8
#define FIN 1528

// ---------------- scratch (device globals; no allocation allowed) ----------------
__device__ float g_qs[LL*HH*24];
__device__ float g_ks[LL*HH*24];
__device__ float g_vg[LL*HH*24];
__device__ float g_qn[LL*HH];
__device__ float g_kn[LL*HH];
__device__ float g_lg[16*LL*LL];        // 16 logit channel planes (i,j)
__device__ float g_ls[LL*HH*LL];        // logits_sum, layout (i,h,j)
__device__ float g_alpha[LL*HH*LL];     // alpha, layout (i,h,j)
__device__ float g_feat[LL*FIN];
__device__ float g_h1[LL*2*DD];
__device__ float g_wt[9*136*128];       // cp weights transposed [tap][cin][cout]
__device__ float g_zsum[136], g_zsq[136];
__device__ float g_zmean[136], g_zrstd[136];
__device__ float g_cmean[16], g_crstd[16];

__device__ __forceinline__ float lrelu(float v){ return v >= 0.f ? v : 0.01f*v; }

// ---------------- kernels ----------------
__global__ void k_zero(){
    int tid = threadIdx.x;
    if (tid < 136){ g_zsum[tid]=0.f; g_zsq[tid]=0.f; }
}

__global__ void k_wtrans(const float* __restrict__ cpw){
    int idx = blockIdx.x*256 + threadIdx.x;
    if (idx < 9*136*128){
        int co  = idx & 127;
        int r   = idx >> 7;
        int cin = r % 136;
        int tap = r / 136;
        g_wt[idx] = cpw[co*1224 + cin*9 + tap];   // cp_w (128,136,3,3)
    }
}

// q/k/v projection + local->global transform + q/k squared norms
__global__ void k_qkv(const float* __restrict__ x, const float* __restrict__ R,
                      const float* __restrict__ t,
                      const float* __restrict__ Wq, const float* __restrict__ Wk,
                      const float* __restrict__ Wv){
    int i = blockIdx.x, which = blockIdx.y, tid = threadIdx.x; // 192 threads
    const float* W = (which==0)?Wq:((which==1)?Wk:Wv);
    __shared__ float xs[256];
    __shared__ float tmp[192];
    __shared__ float outp[192];
    for (int idx=tid; idx<256; idx+=192) xs[idx] = x[i*256+idx];
    __syncthreads();
    float acc = 0.f;
    #pragma unroll 8
    for (int d=0; d<256; d++) acc += xs[d]*W[d*192+tid];
    tmp[tid] = acc;
    __syncthreads();
    if (tid < 64){
        float p0=tmp[tid*3], p1=tmp[tid*3+1], p2=tmp[tid*3+2];
        const float* Ri = R + i*9; const float* ti = t + i*3;
        float q0 = Ri[0]*p0+Ri[1]*p1+Ri[2]*p2 + ti[0];
        float q1 = Ri[3]*p0+Ri[4]*p1+Ri[5]*p2 + ti[1];
        float q2 = Ri[6]*p0+Ri[7]*p1+Ri[8]*p2 + ti[2];
        outp[tid*3]=q0; outp[tid*3+1]=q1; outp[tid*3+2]=q2;
        float* dst = (which==0)?g_qs:((which==1)?g_ks:g_vg);
        dst[i*192+tid*3]=q0; dst[i*192+tid*3+1]=q1; dst[i*192+tid*3+2]=q2;
    }
    __syncthreads();
    if (which < 2 && tid < 8){
        float s=0.f;
        #pragma unroll
        for (int d=0; d<24; d++){ float v=outp[tid*24+d]; s+=v*v; }
        ((which==0)?g_qn:g_kn)[i*8+tid]=s;
    }
}

// pair logits: z @ W_p2h -> planes 0..7 of g_lg
__global__ void k_pairlogits(const float* __restrict__ z, const float* __restrict__ Wp){
    __shared__ float wp[1024];
    __shared__ float zt[32*132];
    __shared__ float ob[32*8];
    int i = blockIdx.x, tid = threadIdx.x;
    for (int idx=tid; idx<1024; idx+=256) wp[idx] = Wp[idx];
    for (int jt=0; jt<512; jt+=32){
        __syncthreads();
        for (int idx=tid; idx<4096; idx+=256){
            int j = idx>>7, p = idx&127;
            zt[j*132+p] = z[(i*512 + jt + j)*128 + p];
        }
        __syncthreads();
        int jl = tid>>3, h = tid&7;
        float acc = 0.f;
        #pragma unroll 8
        for (int p=0; p<128; p++) acc += zt[jl*132+p]*wp[p*8+h];
        ob[jl*8+h] = acc;
        __syncthreads();
        int oc = tid>>5, j2 = tid&31;
        g_lg[oc*262144 + i*512 + jt + j2] = ob[j2*8+oc];
    }
}

// spatial logits: planes 8..15 of g_lg
__global__ void k_spatial(const float* __restrict__ gamma){
    int i = blockIdx.x, tid = threadIdx.x;
    __shared__ float qs[8*25];
    __shared__ float qn_s[8];
    __shared__ float cs[8];
    __shared__ float kt[32*200];
    if (tid < 192){ int h=tid/24, d=tid%24; qs[h*25+d] = g_qs[i*192+tid]; }
    if (tid < 8){
        qn_s[tid] = g_qn[i*8+tid];
        cs[tid] = -gamma[tid]*sqrtf(2.0f/72.0f)*0.5f;
    }
    for (int jt=0; jt<512; jt+=32){
        __syncthreads();
        for (int idx=tid; idx<32*192; idx+=256){
            int j = idx/192, r = idx%192;
            int h = r/24, d = r%24;
            kt[j*200 + h*25 + d] = g_ks[(jt+j)*192 + r];
        }
        __syncthreads();
        int jl = tid>>3, h = tid&7;
        float dot = 0.f;
        #pragma unroll
        for (int d=0; d<24; d++) dot += qs[h*25+d]*kt[jl*200+h*25+d];
        float kn = g_kn[(jt+jl)*8+h];
        float ssd = qn_s[h] + kn - 2.0f*dot;
        g_lg[(8+h)*262144 + i*512 + jt + jl] = ssd*cs[h];
    }
}

// z per-channel stats (for pz instance norm)
__global__ void k_zstats(const float* __restrict__ z){
    int b = blockIdx.x, tid = threadIdx.x;
    int c = tid & 127, half = tid >> 7;
    long base = (long)b*4096;
    float s=0.f, s2=0.f;
    for (int r=half; r<4096; r+=2){
        float v = z[(base+r)*128 + c];
        s += v; s2 += v*v;
    }
    __shared__ float sh[256], sh2[256];
    sh[tid]=s; sh2[tid]=s2;
    __syncthreads();
    if (tid < 128){
        atomicAdd(&g_zsum[c], sh[tid]+sh[tid+128]);
        atomicAdd(&g_zsq[c],  sh2[tid]+sh2[tid+128]);
    }
}

// lg per-channel mean/rstd (instance norm for conv_ca input)
__global__ void k_lgstats(){
    int ch = blockIdx.x, tid = threadIdx.x;  // 512 threads
    const float* p = g_lg + ch*262144;
    float s=0.f, s2=0.f;
    for (int idx=tid; idx<262144; idx+=512){ float v=p[idx]; s+=v; s2+=v*v; }
    __shared__ float sh[512], sh2[512];
    sh[tid]=s; sh2[tid]=s2; __syncthreads();
    for (int st=256; st>0; st>>=1){
        if (tid<st){ sh[tid]+=sh[tid+st]; sh2[tid]+=sh2[tid+st]; }
        __syncthreads();
    }
    if (tid==0){
        float m = sh[0]/262144.0f;
        float var = sh2[0]/262144.0f - m*m;
        g_cmean[ch]=m; g_crstd[ch]=rsqrtf(var+1e-5f);
    }
}

// conv ca: inorm(lg) -> 3x3 conv (16->8) -> leaky -> g_ls (i,h,j)
__global__ void k_conv_ca(const float* __restrict__ caw, const float* __restrict__ cab){
    int bid = blockIdx.x;
    int i = bid>>3, jt = (bid&7)<<6;
    int tid = threadIdx.x;
    __shared__ float cw[1152];
    __shared__ float cb[8];
    __shared__ float sg[16*67];
    for (int idx=tid; idx<1152; idx+=256) cw[idx]=caw[idx];
    if (tid<8) cb[tid]=cab[tid];
    int px = tid & 63, g2 = tid >> 6;
    int o0 = g2*2, o1 = o0+1;
    float a0=0.f, a1=0.f;
    for (int di=0; di<3; di++){
        int row = i + di - 1;
        __syncthreads();
        if (row >= 0 && row < 512){
            for (int idx=tid; idx<16*66; idx+=256){
                int c = idx/66, jj = idx%66;
                int col = jt - 1 + jj;
                float v = 0.f;
                if (col>=0 && col<512) v = (g_lg[c*262144 + row*512 + col]-g_cmean[c])*g_crstd[c];
                sg[c*67+jj]=v;
            }
        } else {
            for (int idx=tid; idx<16*67; idx+=256) sg[idx]=0.f;
        }
        __syncthreads();
        for (int dj=0; dj<3; dj++){
            #pragma unroll
            for (int c=0; c<16; c++){
                float a = sg[c*67 + px + dj];
                a0 += a*cw[o0*144 + c*9 + di*3 + dj];
                a1 += a*cw[o1*144 + c*9 + di*3 + dj];
            }
        }
    }
    a0 = lrelu(a0 + cb[o0]);
    a1 = lrelu(a1 + cb[o1]);
    g_ls[i*4096 + o0*512 + jt+px] = a0;
    g_ls[i*4096 + o1*512 + jt+px] = a1;
}

// softmax over j per (i,h); also alpha channel stats
__global__ void k_softmax(){
    int bid = blockIdx.x; int i = bid>>3, h = bid&7;
    int tid = threadIdx.x;
    const float* row = g_ls + i*4096 + h*512;
    float v0 = row[tid], v1 = row[tid+256];
    __shared__ float sh[256];
    sh[tid] = fmaxf(v0,v1); __syncthreads();
    for (int st=128; st>0; st>>=1){ if(tid<st) sh[tid]=fmaxf(sh[tid],sh[tid+st]); __syncthreads(); }
    float mx = sh[0]; __syncthreads();
    float e0 = expf(v0-mx), e1 = expf(v1-mx);
    sh[tid] = e0+e1; __syncthreads();
    for (int st=128; st>0; st>>=1){ if(tid<st) sh[tid]+=sh[tid+st]; __syncthreads(); }
    float inv = 1.0f/sh[0]; __syncthreads();
    float a0 = e0*inv, a1 = e1*inv;
    float* orow = g_alpha + i*4096 + h*512;
    orow[tid]=a0; orow[tid+256]=a1;
    // stats (sum and sumsq of alpha over this row)
    sh[tid]=a0+a1; __syncthreads();
    for (int st=128; st>0; st>>=1){ if(tid<st) sh[tid]+=sh[tid+st]; __syncthreads(); }
    float ssum = sh[0]; __syncthreads();
    sh[tid]=a0*a0+a1*a1; __syncthreads();
    for (int st=128; st>0; st>>=1){ if(tid<st) sh[tid]+=sh[tid+st]; __syncthreads(); }
    if (tid==0){
        atomicAdd(&g_zsum[128+h], ssum);
        atomicAdd(&g_zsq[128+h], sh[0]);
    }
}

__global__ void k_statfin(){
    int tid = threadIdx.x;
    if (tid < 136){
        float cnt = 262144.0f;
        float m = g_zsum[tid]/cnt;
        float var = g_zsq[tid]/cnt - m*m;
        g_zmean[tid]=m; g_zrstd[tid]=rsqrtf(var+1e-5f);
    }
}

// feat_p2n = alpha^T z  (per i: 8x512 * 512x128)
__global__ void k_featp2n(const float* __restrict__ z){
    int i = blockIdx.x, tid = threadIdx.x;
    __shared__ float al[8*513];
    __shared__ float zt[16*132];
    for (int idx=tid; idx<4096; idx+=256){ int h=idx>>9, j=idx&511; al[h*513+j]=g_alpha[i*4096+idx]; }
    int h = tid>>5, p4 = (tid&31)*4;
    float acc0=0.f, acc1=0.f, acc2=0.f, acc3=0.f;
    for (int jt=0; jt<512; jt+=16){
        __syncthreads();
        for (int idx=tid; idx<2048; idx+=256){ int j=idx>>7, p=idx&127; zt[j*132+p]=z[(i*512+jt+j)*128+p]; }
        __syncthreads();
        #pragma unroll
        for (int j=0; j<16; j++){
            float a = al[h*513 + jt + j];
            const float4 zr = *(const float4*)&zt[j*132 + p4];
            acc0 += a*zr.x; acc1 += a*zr.y; acc2 += a*zr.z; acc3 += a*zr.w;
        }
    }
    float* dst = &g_feat[i*1528 + h*128 + p4];
    dst[0]=acc0; dst[1]=acc1; dst[2]=acc2; dst[3]=acc3;
}

// v & p_CB aggregation + g2l + norms/dirs -> feat_all[1024:1528]
__global__ void k_aggr(const float* __restrict__ R, const float* __restrict__ t,
                       const float* __restrict__ pcb){
    int i = blockIdx.x, tid = threadIdx.x;
    __shared__ float al[8*513];
    __shared__ float ag[216];
    for (int idx=tid; idx<4096; idx+=256){ int h=idx>>9, j=idx&511; al[h*513+j]=g_alpha[i*4096+idx]; }
    __syncthreads();
    if (tid < 192){
        int h = tid/24;
        float s=0.f;
        #pragma unroll 4
        for (int j=0; j<512; j++) s += al[h*513+j]*g_vg[j*192 + tid];
        ag[tid]=s;
    } else if (tid < 216){
        int idx = tid-192; int h = idx/3, c = idx%3;
        float s=0.f;
        #pragma unroll 4
        for (int j=0; j<512; j++) s += al[h*513+j]*pcb[j*3+c];
        ag[tid]=s;
    }
    __syncthreads();
    const float* Ri = R + i*9; const float* ti = t + i*3;
    if (tid < 64){
        float q0=ag[tid*3]-ti[0], q1=ag[tid*3+1]-ti[1], q2=ag[tid*3+2]-ti[2];
        float p0 = Ri[0]*q0+Ri[3]*q1+Ri[6]*q2;
        float p1 = Ri[1]*q0+Ri[4]*q1+Ri[7]*q2;
        float p2 = Ri[2]*q0+Ri[5]*q1+Ri[8]*q2;
        float fn = sqrtf(p0*p0+p1*p1+p2*p2);
        float invn = 1.0f/(fn+1e-6f);
        float* f = &g_feat[i*1528 + 1024];
        f[tid*3]=p0; f[tid*3+1]=p1; f[tid*3+2]=p2;
        f[192+tid]=fn;
        f[256+tid*3]=p0*invn; f[256+tid*3+1]=p1*invn; f[256+tid*3+2]=p2*invn;
    } else if (tid < 72){
        int h = tid-64;
        float q0=ag[192+h*3]-ti[0], q1=ag[192+h*3+1]-ti[1], q2=ag[192+h*3+2]-ti[2];
        float p0 = Ri[0]*q0+Ri[3]*q1+Ri[6]*q2;
        float p1 = Ri[1]*q0+Ri[4]*q1+Ri[7]*q2;
        float p2 = Ri[2]*q0+Ri[5]*q1+Ri[8]*q2;
        float fn = sqrtf(p0*p0+p1*p1+p2*p2);
        float invn = 1.0f/(fn+1e-6f);
        float* f = &g_feat[i*1528 + 1472];
        f[h*3]=p0; f[h*3+1]=p1; f[h*3+2]=p2;
        f[24+h]=fn;
        f[32+h*3]=p0*invn; f[32+h*3+1]=p1*invn; f[32+h*3+2]=p2*invn;
    }
}

// feat_all(512x1528) @ W1(1528x512) + b1 -> g_h1
__global__ void k_gemm1(const float* __restrict__ W1, const float* __restrict__ b1){
    int i0 = blockIdx.x*16, tid = threadIdx.x;
    __shared__ float fs[128];
    float acc[16][2];
    #pragma unroll
    for (int r=0;r<16;r++){ acc[r][0]=0.f; acc[r][1]=0.f; }
    for (int k0=0; k0<1528; k0+=8){
        __syncthreads();
        if (tid < 128){ int r=tid>>3, kk=tid&7; fs[tid]=g_feat[(i0+r)*1528 + k0 + kk]; }
        __syncthreads();
        #pragma unroll
        for (int kk=0; kk<8; kk++){
            float w0 = W1[(k0+kk)*512 + tid];
            float w1 = W1[(k0+kk)*512 + 256 + tid];
            #pragma unroll
            for (int r=0; r<16; r++){
                float f = fs[r*8+kk];
                acc[r][0] += f*w0; acc[r][1] += f*w1;
            }
        }
    }
    float bb0 = b1[tid], bb1 = b1[tid+256];
    for (int r=0; r<16; r++){
        g_h1[(i0+r)*512 + tid] = acc[r][0] + bb0;
        g_h1[(i0+r)*512 + 256 + tid] = acc[r][1] + bb1;
    }
}

// LN over 512 + leaky, in place on g_h1
__global__ void k_ln1(const float* __restrict__ g, const float* __restrict__ b){
    int i = blockIdx.x, tid = threadIdx.x;
    float v0 = g_h1[i*512+tid], v1 = g_h1[i*512+256+tid];
    __shared__ float sh[256];
    sh[tid]=v0+v1; __syncthreads();
    for (int st=128; st>0; st>>=1){ if(tid<st) sh[tid]+=sh[tid+st]; __syncthreads(); }
    float m = sh[0]/512.0f; __syncthreads();
    float d0=v0-m, d1=v1-m;
    sh[tid]=d0*d0+d1*d1; __syncthreads();
    for (int st=128; st>0; st>>=1){ if(tid<st) sh[tid]+=sh[tid+st]; __syncthreads(); }
    float rstd = rsqrtf(sh[0]/512.0f + 1e-5f);
    float y0 = lrelu(d0*rstd*g[tid] + b[tid]);
    float y1 = lrelu(d1*rstd*g[tid+256] + b[tid+256]);
    g_h1[i*512+tid]=y0; g_h1[i*512+256+tid]=y1;
}

// h1 @ W2 + b2, residual, LN -> x_out
__global__ void k_out(const float* __restrict__ x, const float* __restrict__ W2,
                      const float* __restrict__ b2, const float* __restrict__ lng,
                      const float* __restrict__ lnb, float* __restrict__ out){
    int i = blockIdx.x, tid = threadIdx.x;
    __shared__ float hs[512];
    hs[tid]=g_h1[i*512+tid]; hs[tid+256]=g_h1[i*512+256+tid];
    __syncthreads();
    float acc = 0.f;
    #pragma unroll 8
    for (int k=0; k<512; k++) acc += hs[k]*W2[k*256+tid];
    float s = acc + b2[tid] + x[i*256+tid];
    __shared__ float sh[256];
    sh[tid]=s; __syncthreads();
    for (int st=128; st>0; st>>=1){ if(tid<st) sh[tid]+=sh[tid+st]; __syncthreads(); }
    float m = sh[0]/256.0f; __syncthreads();
    float d = s-m;
    sh[tid]=d*d; __syncthreads();
    for (int st=128; st>0; st>>=1){ if(tid<st) sh[tid]+=sh[tid+st]; __syncthreads(); }
    float rstd = rsqrtf(sh[0]/256.0f + 1e-5f);
    out[i*256+tid] = d*rstd*lng[tid] + lnb[tid];
}

// pair conv: inorm(concat(z,alpha)) -> 3x3 conv 136->128 -> leaky -> pair_out
__global__ void __launch_bounds__(256) k_conv_cp(const float* __restrict__ z,
                                                 const float* __restrict__ cpb,
                                                 float* __restrict__ pout){
    __shared__ float stage[136*67];   // 36448 B
    __shared__ float bw[17*128];      //  8704 B
    int bid = blockIdx.x;
    int i = bid>>3, jt = (bid&7)<<6;
    int tid = threadIdx.x;
    int pg = tid & 15, cg = tid >> 4;  // pg: 4 pixels each, cg: 8 couts each
    float acc[4][8];
    #pragma unroll
    for (int u=0;u<4;u++)
        #pragma unroll
        for (int o=0;o<8;o++) acc[u][o]=0.f;

    for (int di=0; di<3; di++){
        int row = i + di - 1;
        if (row < 0 || row >= 512) continue;   // uniform across block
        __syncthreads();
        for (int idx=tid; idx<66*136; idx+=256){
            int jj = idx/136, k = idx%136;
            int col = jt - 1 + jj;
            float v = 0.f;
            if (col>=0 && col<512){
                if (k < 128) v = (z[(row*512+col)*128 + k] - g_zmean[k])*g_zrstd[k];
                else         v = (g_alpha[row*4096 + (k-128)*512 + col] - g_zmean[k])*g_zrstd[k];
            }
            stage[k*67+jj]=v;
        }
        __syncthreads();
        for (int dj=0; dj<3; dj++){
            int jb = pg*4 + dj;
            for (int c0=0; c0<136; c0+=17){
                __syncthreads();
                {
                    const float4* src = (const float4*)(g_wt + ((di*3+dj)*136 + c0)*128);
                    float4* dstv = (float4*)bw;
                    for (int idx=tid; idx<544; idx+=256) dstv[idx]=src[idx];
                }
                __syncthreads();
                #pragma unroll
                for (int kk=0; kk<17; kk++){
                    int krow = (c0+kk)*67 + jb;
                    float a0=stage[krow], a1=stage[krow+1], a2=stage[krow+2], a3=stage[krow+3];
                    const float4* b4 = (const float4*)&bw[kk*128 + cg*8];
                    float4 bA = b4[0], bB = b4[1];
                    acc[0][0]+=a0*bA.x; acc[0][1]+=a0*bA.y; acc[0][2]+=a0*bA.z; acc[0][3]+=a0*bA.w;
                    acc[0][4]+=a0*bB.x; acc[0][5]+=a0*bB.y; acc[0][6]+=a0*bB.z; acc[0][7]+=a0*bB.w;
                    acc[1][0]+=a1*bA.x; acc[1][1]+=a1*bA.y; acc[1][2]+=a1*bA.z; acc[1][3]+=a1*bA.w;
                    acc[1][4]+=a1*bB.x; acc[1][5]+=a1*bB.y; acc[1][6]+=a1*bB.z; acc[1][7]+=a1*bB.w;
                    acc[2][0]+=a2*bA.x; acc[2][1]+=a2*bA.y; acc[2][2]+=a2*bA.z; acc[2][3]+=a2*bA.w;
                    acc[2][4]+=a2*bB.x; acc[2][5]+=a2*bB.y; acc[2][6]+=a2*bB.z; acc[2][7]+=a2*bB.w;
                    acc[3][0]+=a3*bA.x; acc[3][1]+=a3*bA.y; acc[3][2]+=a3*bA.z; acc[3][3]+=a3*bA.w;
                    acc[3][4]+=a3*bB.x; acc[3][5]+=a3*bB.y; acc[3][6]+=a3*bB.z; acc[3][7]+=a3*bB.w;
                }
            }
        }
    }
    float cb[8];
    #pragma unroll
    for (int o=0;o<8;o++) cb[o]=cpb[cg*8+o];
    #pragma unroll
    for (int u=0;u<4;u++){
        int j = jt + pg*4 + u;
        float4 r0, r1;
        r0.x = lrelu(acc[u][0]+cb[0]); r0.y = lrelu(acc[u][1]+cb[1]);
        r0.z = lrelu(acc[u][2]+cb[2]); r0.w = lrelu(acc[u][3]+cb[3]);
        r1.x = lrelu(acc[u][4]+cb[4]); r1.y = lrelu(acc[u][5]+cb[5]);
        r1.z = lrelu(acc[u][6]+cb[6]); r1.w = lrelu(acc[u][7]+cb[7]);
        float* dst = pout + (i*512+j)*128 + cg*8;
        ((float4*)dst)[0]=r0; ((float4*)dst)[1]=r1;
    }
}

// ---------------- launch ----------------
extern "C" void kernel_launch(void* const* d_in, const int* in_sizes, int n_in,
                              void* d_out, int out_size){
    const float* R    = (const float*)d_in[0];
    const float* t    = (const float*)d_in[1];
    const float* pcb  = (const float*)d_in[2];
    const float* x    = (const float*)d_in[3];
    const float* z    = (const float*)d_in[4];
    const float* Wp   = (const float*)d_in[5];
    const float* gamma= (const float*)d_in[6];
    const float* Wq   = (const float*)d_in[7];
    const float* Wk   = (const float*)d_in[8];
    const float* Wv   = (const float*)d_in[9];
    const float* W1   = (const float*)d_in[10];
    const float* b1   = (const float*)d_in[11];
    const float* ln1g = (const float*)d_in[12];
    const float* ln1b = (const float*)d_in[13];
    const float* W2   = (const float*)d_in[14];
    const float* b2   = (const float*)d_in[15];
    const float* caw  = (const float*)d_in[16];
    const float* cab  = (const float*)d_in[17];
    const float* lng  = (const float*)d_in[18];
    const float* lnb  = (const float*)d_in[19];
    const float* cpw  = (const float*)d_in[20];
    const float* cpb  = (const float*)d_in[21];
    float* out = (float*)d_out;

    k_zero<<<1,256>>>();
    k_wtrans<<<612,256>>>(cpw);
    k_qkv<<<dim3(512,3),192>>>(x,R,t,Wq,Wk,Wv);
    k_pairlogits<<<512,256>>>(z,Wp);
    k_spatial<<<512,256>>>(gamma);
    k_zstats<<<64,256>>>(z);
    k_lgstats<<<16,512>>>();
    k_conv_ca<<<4096,256>>>(caw,cab);
    k_softmax<<<4096,256>>>();
    k_statfin<<<1,256>>>();
    k_featp2n<<<512,256>>>(z);
    k_aggr<<<512,256>>>(R,t,pcb);
    k_gemm1<<<32,256>>>(W1,b1);
    k_ln1<<<512,256>>>(ln1g,ln1b);
    k_out<<<512,256>>>(x,W2,b2,lng,lnb,out);
    k_conv_cp<<<4096,256>>>(z, cpb, out + 131072);
}